// round 15
// baseline (speedup 1.0000x reference)
#include <cuda_runtime.h>
#include <cuda_fp16.h>
#include <cstdint>

#define BB   8
#define SS   512
#define HH   16
#define DD   64
#define HIDN 1024
#define BH   (BB*HH)   // 128

// ---------------- scratch (device globals, fp16 packed as half2 words) -----
__device__ uint32_t g_q[BH*SS*DD/2];            // [b,h,s,d/2] 8MB
__device__ uint32_t g_k[BH*SS*DD/2];
__device__ uint32_t g_v[BH*SS*DD/2];
__device__ uint32_t g_pos[HH*1024*DD/2];        // [h,p,d/2]   2MB
__device__ uint32_t g_hs16[BB*SS*HIDN/2];       // fp16 hidden_states 8MB
__device__ uint32_t g_rel16[1024*HIDN/2];       // fp16 rel_emb 2MB
__device__ uint32_t g_w16[4][HIDN*HIDN/2];      // fp16 Wq,Wk,Wv,Wpk 4x2MB

// ---------------- helpers ---------------------------------------------------
__device__ __forceinline__ uint32_t packh2(float lo, float hi) {
    uint32_t u;
    asm("cvt.rn.f16x2.f32 %0, %1, %2;" : "=r"(u) : "f"(hi), "f"(lo));
    return u;
}
__device__ __forceinline__ uint32_t smaddr(const void* p) {
    uint32_t a;
    asm("{ .reg .u64 t; cvta.to.shared.u64 t, %1; cvt.u32.u64 %0, t; }" : "=r"(a) : "l"(p));
    return a;
}
__device__ __forceinline__ void mma_f16(float c[4], const uint32_t a[4], const uint32_t b[2]) {
    asm volatile("mma.sync.aligned.m16n8k16.row.col.f32.f16.f16.f32 "
        "{%0,%1,%2,%3}, {%4,%5,%6,%7}, {%8,%9}, {%0,%1,%2,%3};"
        : "+f"(c[0]), "+f"(c[1]), "+f"(c[2]), "+f"(c[3])
        : "r"(a[0]), "r"(a[1]), "r"(a[2]), "r"(a[3]), "r"(b[0]), "r"(b[1]));
}
__device__ __forceinline__ void ldm_x4(uint32_t& r0, uint32_t& r1, uint32_t& r2, uint32_t& r3,
                                       uint32_t addr) {
    asm volatile("ldmatrix.sync.aligned.m8n8.x4.shared.b16 {%0,%1,%2,%3}, [%4];"
        : "=r"(r0), "=r"(r1), "=r"(r2), "=r"(r3) : "r"(addr));
}
__device__ __forceinline__ void ldm_x4_t(uint32_t& r0, uint32_t& r1, uint32_t& r2, uint32_t& r3,
                                         uint32_t addr) {
    asm volatile("ldmatrix.sync.aligned.m8n8.x4.trans.shared.b16 {%0,%1,%2,%3}, [%4];"
        : "=r"(r0), "=r"(r1), "=r"(r2), "=r"(r3) : "r"(addr));
}
__device__ __forceinline__ void cp16(uint32_t smem_dst, const void* gsrc) {
    asm volatile("cp.async.ca.shared.global [%0], [%1], 16;" :: "r"(smem_dst), "l"(gsrc));
}
#define CP_COMMIT() asm volatile("cp.async.commit_group;" ::: "memory")
#define CP_WAIT0()  asm volatile("cp.async.wait_group 0;" ::: "memory")
#define CP_WAIT1()  asm volatile("cp.async.wait_group 1;" ::: "memory")

// fragment-base lane offsets
#define A_ROW(lane)  ((lane) & 15)
#define A_COL(lane)  ((((lane) >> 4) & 1) << 2)
#define B_ROW(lane)  (((((lane) >> 4) & 1) << 3) + ((lane) & 7))
#define B_COL(lane)  ((((lane) >> 3) & 1) << 2)

// ---------------- precvt: fp32 -> fp16 (one-time, 32B/thread) ---------------
__global__ __launch_bounds__(256) void precvt(
    const float* __restrict__ hs, const float* __restrict__ rel,
    const float* __restrict__ Wq, const float* __restrict__ Wk,
    const float* __restrict__ Wv, const float* __restrict__ Wpk)
{
    const int seg = blockIdx.y;
    const float* src;
    uint32_t* dst;
    int n;
    switch (seg) {
        case 0: src = hs;  dst = g_hs16;  n = BB*SS*HIDN; break;
        case 1: src = rel; dst = g_rel16; n = 1024*HIDN;  break;
        case 2: src = Wq;  dst = g_w16[0]; n = HIDN*HIDN; break;
        case 3: src = Wk;  dst = g_w16[1]; n = HIDN*HIDN; break;
        case 4: src = Wv;  dst = g_w16[2]; n = HIDN*HIDN; break;
        default: src = Wpk; dst = g_w16[3]; n = HIDN*HIDN; break;
    }
    const int i = (blockIdx.x * 256 + threadIdx.x) * 8;
    if (i >= n) return;
    const float4 x = *(const float4*)(src + i);
    const float4 y = *(const float4*)(src + i + 4);
    *(uint4*)&dst[i >> 1] = make_uint4(packh2(x.x, x.y), packh2(x.z, x.w),
                                       packh2(y.x, y.y), packh2(y.z, y.w));
}

// ---------------- fp16 HMMA projection GEMM (3-stage cp.async pipeline) ----
// K-chunk 64, stages of (A 128x36 + B 128x36) words = 36864 B; 3 stages.
#define GEMM_SMEM (3 * 9216 * 4)   // 110592 B (x2 = 221184 <= 228KB/SM)

__global__ __launch_bounds__(256, 2) void gemm_tc(
    const float* __restrict__ bq, const float* __restrict__ bk,
    const float* __restrict__ bv, const float* __restrict__ bpk)
{
    extern __shared__ uint32_t smg[];

    const int which = blockIdx.z;
    if (which == 3 && blockIdx.y >= 8) return;

    const uint32_t* Ag = ((which == 3) ? g_rel16 : g_hs16);
    const uint32_t* Bg = g_w16[which];
    const float* bias = (which == 0) ? bq : (which == 1) ? bk : (which == 2) ? bv : bpk;
    uint32_t* outp    = (which == 0) ? g_q : (which == 1) ? g_k : (which == 2) ? g_v : g_pos;

    const int bm = blockIdx.y * 128;
    const int bn = blockIdx.x * 128;
    const int tid = threadIdx.x;
    const int wid = tid >> 5, lane = tid & 31;
    const int wm = wid >> 1, wn = wid & 1;
    const int g = lane >> 2, t = lane & 3;

    Ag += (size_t)bm * (HIDN/2);
    Bg += (size_t)bn * (HIDN/2);

    float acc[2][8][4];
#pragma unroll
    for (int mt = 0; mt < 2; mt++)
#pragma unroll
        for (int nt = 0; nt < 8; nt++)
#pragma unroll
            for (int i = 0; i < 4; i++) acc[mt][nt][i] = 0.f;

    const uint32_t smBase = smaddr(smg);
    const uint32_t aFB = smBase + (uint32_t)(((wm*32 + A_ROW(lane))*36 + A_COL(lane)) * 4);
    const uint32_t bFB = smBase + (uint32_t)((4608 + (wn*64 + B_ROW(lane))*36 + B_COL(lane)) * 4);

    // prologue: fill stages 0 and 1 (two groups)
#pragma unroll
    for (int s = 0; s < 2; s++) {
        const uint32_t off = (uint32_t)(s * 9216 * 4);
        const int kk = s * 32;
#pragma unroll
        for (int i = 0; i < 4; i++) {
            const int u = tid + i*256, row = u >> 3, c = u & 7;
            cp16(smBase + off + (uint32_t)(row*144 + c*16),          Ag + (size_t)row*512 + kk + c*4);
            cp16(smBase + off + (uint32_t)(4608*4 + row*144 + c*16), Bg + (size_t)row*512 + kk + c*4);
        }
        CP_COMMIT();
    }

    int stage = 0;
    for (int kc = 0; kc < 16; kc++) {
        if (kc < 15) { CP_WAIT1(); } else { CP_WAIT0(); }
        __syncthreads();   // stage kc visible; all warps past iter kc-1 reads

        if (kc + 2 < 16) {
            const int snext = (stage + 2 >= 3) ? (stage - 1) : (stage + 2);
            const uint32_t off = (uint32_t)(snext * 9216 * 4);
            const int kk = (kc + 2) * 32;
#pragma unroll
            for (int i = 0; i < 4; i++) {
                const int u = tid + i*256, row = u >> 3, c = u & 7;
                cp16(smBase + off + (uint32_t)(row*144 + c*16),          Ag + (size_t)row*512 + kk + c*4);
                cp16(smBase + off + (uint32_t)(4608*4 + row*144 + c*16), Bg + (size_t)row*512 + kk + c*4);
            }
            CP_COMMIT();
        }

        const uint32_t boff = (uint32_t)(stage * 9216 * 4);
#pragma unroll
        for (int ks = 0; ks < 4; ks++) {
            uint32_t a[2][4], b[8][2];
#pragma unroll
            for (int mt = 0; mt < 2; mt++)
                ldm_x4(a[mt][0], a[mt][1], a[mt][2], a[mt][3],
                       aFB + boff + (uint32_t)(mt*16*36*4 + ks*32));
#pragma unroll
            for (int ntp = 0; ntp < 4; ntp++)
                ldm_x4(b[2*ntp][0], b[2*ntp][1], b[2*ntp+1][0], b[2*ntp+1][1],
                       bFB + boff + (uint32_t)(ntp*16*36*4 + ks*32));
#pragma unroll
            for (int mt = 0; mt < 2; mt++)
#pragma unroll
                for (int nt = 0; nt < 8; nt++)
                    mma_f16(acc[mt][nt], a[mt], b[nt]);
        }
        stage = (stage + 1 >= 3) ? 0 : (stage + 1);
    }

#pragma unroll
    for (int mt = 0; mt < 2; mt++) {
#pragma unroll
        for (int nt = 0; nt < 8; nt++) {
            const int n = bn + wn*64 + nt*8 + 2*t;
            const float bv0 = bias[n], bv1 = bias[n+1];
#pragma unroll
            for (int half = 0; half < 2; half++) {
                const int m = bm + wm*32 + mt*16 + g + half*8;
                const float v0 = acc[mt][nt][half*2+0] + bv0;
                const float v1 = acc[mt][nt][half*2+1] + bv1;
                size_t oi;
                if (which < 3) {
                    const int b_ = m >> 9, s = m & 511, h = n >> 6, d = n & 63;
                    oi = (((size_t)(b_*HH + h))*SS + s)*DD + d;
                } else {
                    oi = (((size_t)(n >> 6))*1024 + m)*DD + (n & 63);
                }
                outp[oi >> 1] = packh2(v0, v1);
            }
        }
    }
}

// ---------------- fused flash kernel (unchanged from R14) ------------------
#define FL_SMEM (27584 * 4)   // x2 = 220672 <= 228KB/SM

__global__ __launch_bounds__(320, 2) void flash_tc(const float* __restrict__ mask,
                                                   float* __restrict__ out)
{
    extern __shared__ uint32_t smw[];
    uint32_t* Qs  = smw;                    // [64 i][36 w]
    uint32_t* Ks  = smw + 2304;             // [64 j][36 w]
    uint32_t* Ps  = smw + 4608;             // [128 p][36 w]
    uint32_t* Vs  = smw + 9216;             // [64 j][36 w] row-major V
    uint32_t* Pt2 = smw + 11520;            // [64 i][36 w] P~ f16
    float*    SsF = (float*)(smw + 13824);  // [64][68] CC
    float*    B1  = (float*)(smw + 18176);  // [64][68] sheared CPF
    float*    B2  = (float*)(smw + 22528);  // [64][68] sheared PCF
    float* sm_m     = (float*)(smw + 26880);
    float* sm_l     = sm_m + 64;
    float* sm_scale = sm_m + 128;
    float* sm_mask  = sm_m + 192;           // [512] full mask row

    const int i0 = blockIdx.x * 64;
    const int bh = blockIdx.y;
    const int b_ = bh >> 4, h = bh & 15;
    const int tid = threadIdx.x;
    const int wid = tid >> 5, lane = tid & 31;
    const int g = lane >> 2, t = lane & 3;
    const int wm = wid >> 1, wn = wid & 1;

    const uint32_t* q32 = g_q + ((size_t)bh*SS + i0) * (DD/2);
    const uint32_t* k32 = g_k + (size_t)bh*SS*(DD/2);
    const uint32_t* v32 = g_v + (size_t)bh*SS*(DD/2);
    const uint32_t* p32 = g_pos + (size_t)h * 1024 * (DD/2);

    const uint32_t smQs = smaddr(Qs), smKs = smaddr(Ks), smPs = smaddr(Ps), smVs = smaddr(Vs);

    for (int u = tid; u < 512; u += 320)
        sm_mask[u] = mask[(size_t)b_*SS + u];
    if (tid < 256) {
#pragma unroll
        for (int i = 0; i < 2; i++) {
            const int u = tid + i*256, row = u >> 3, c = u & 7;
            cp16(smQs + (uint32_t)(row*144 + c*16), q32 + row*32 + c*4);
            cp16(smKs + (uint32_t)(row*144 + c*16), k32 + row*32 + c*4);
        }
        const int base0 = i0 + 449;
#pragma unroll
        for (int i = 0; i < 4; i++) {
            const int u = tid + i*256, pr = u >> 3, c = u & 7;
            int grow = base0 + pr;
            grow = grow < 0 ? 0 : (grow > 1023 ? 1023 : grow);
            cp16(smPs + (uint32_t)(pr*144 + c*16), p32 + grow*32 + c*4);
        }
        CP_COMMIT();
    }
    if (tid < 64) { sm_m[tid] = -1e30f; sm_l[tid] = 0.f; }

    float acc_o[4][4];
#pragma unroll
    for (int nt = 0; nt < 4; nt++)
#pragma unroll
        for (int e = 0; e < 4; e++) acc_o[nt][e] = 0.f;

    const uint32_t* Ap; const uint32_t* Bp;
    int Arow, Brow;
    int kind;
    if (wid < 2)      { Ap = Qs; Arow = wid*32;          Bp = Ks; Brow = 0;                 kind = 0; }
    else if (wid < 6) { Ap = Qs; Arow = ((wid-2)&1)*32;  Bp = Ps; Brow = ((wid-2)>>1)*64;   kind = 1; }
    else              { Ap = Ps; Arow = (wid-6)*32;      Bp = Ks; Brow = 0;                 kind = 2; }

    const uint32_t aFB = smaddr(&Ap[(Arow + A_ROW(lane))*36 + A_COL(lane)]);
    const uint32_t bFB = smaddr(&Bp[(Brow + B_ROW(lane))*36 + B_COL(lane)]);
    const uint32_t aPV = smaddr(&Pt2[(wm*16 + A_ROW(lane))*36 + A_COL(lane)]);
    const uint32_t bPVt = smVs
        + (uint32_t)((((lane >> 3) & 1) * 8 + (lane & 7)) * 144
                     + ((lane >> 4) & 1) * 16 + wn * 64);

    const float s1 = 0.14433756729740643f;      // 1/sqrt(48)

    for (int j0 = 0; j0 < SS; j0 += 64) {
        __syncthreads();

        if (tid < 256) {
            const uint32_t* vc32 = v32 + (size_t)j0 * 32;
#pragma unroll
            for (int i = 0; i < 2; i++) {
                const int u = tid + i*256, row = u >> 3, c = u & 7;
                cp16(smVs + (uint32_t)(row*144 + c*16), vc32 + row*32 + c*4);
            }
            CP_COMMIT();
            CP_WAIT1();    // drain K/P_cur; V_cur stays in flight
        }
        __syncthreads();

#pragma unroll
        for (int hN = 0; hN < 2; hN++) {
            float acc[2][4][4];
#pragma unroll
            for (int mt = 0; mt < 2; mt++)
#pragma unroll
                for (int nt = 0; nt < 4; nt++)
#pragma unroll
                    for (int e = 0; e < 4; e++) acc[mt][nt][e] = 0.f;

#pragma unroll
            for (int ks = 0; ks < 4; ks++) {
                uint32_t a[2][4], b[4][2];
#pragma unroll
                for (int mt = 0; mt < 2; mt++)
                    ldm_x4(a[mt][0], a[mt][1], a[mt][2], a[mt][3],
                           aFB + (uint32_t)(mt*16*36*4 + ks*32));
#pragma unroll
                for (int ntp = 0; ntp < 2; ntp++)
                    ldm_x4(b[2*ntp][0], b[2*ntp][1], b[2*ntp+1][0], b[2*ntp+1][1],
                           bFB + (uint32_t)((hN*32 + ntp*16)*36*4 + ks*32));
#pragma unroll
                for (int mt = 0; mt < 2; mt++)
#pragma unroll
                    for (int nt = 0; nt < 4; nt++)
                        mma_f16(acc[mt][nt], a[mt], b[nt]);
            }

            if (kind == 0) {
#pragma unroll
                for (int mt = 0; mt < 2; mt++)
#pragma unroll
                    for (int nt = 0; nt < 4; nt++) {
                        const int r0 = Arow + mt*16 + g;
                        const int c0 = (hN*4 + nt)*8 + 2*t;
                        *(float2*)&SsF[r0*68 + c0]     = make_float2(acc[mt][nt][0], acc[mt][nt][1]);
                        *(float2*)&SsF[(r0+8)*68 + c0] = make_float2(acc[mt][nt][2], acc[mt][nt][3]);
                    }
            } else if (kind == 1) {
#pragma unroll
                for (int mt = 0; mt < 2; mt++)
#pragma unroll
                    for (int nt = 0; nt < 4; nt++) {
                        const int ai0 = Arow + mt*16 + g;
                        const int p0 = Brow + (hN*4 + nt)*8 + 2*t;
#pragma unroll
                        for (int e = 0; e < 4; e++) {
                            const int ai = ai0 + (e >> 1)*8;
                            const int p  = p0 + (e & 1);
                            const int cj = ai - p + 63;
                            if ((unsigned)cj < 64u)
                                B1[ai*68 + cj] = acc[mt][nt][e];
                        }
                    }
            } else {
#pragma unroll
                for (int mt = 0; mt < 2; mt++)
#pragma unroll
                    for (int nt = 0; nt < 4; nt++) {
                        const int r0 = Arow + mt*16 + g;
                        const int c0 = (hN*4 + nt)*8 + 2*t;
#pragma unroll
                        for (int e = 0; e < 4; e++) {
                            const int r  = r0 + (e >> 1)*8;
                            const int cj = c0 + (e & 1);
                            const int ai = r + cj - 63;
                            if ((unsigned)ai < 64u)
                                B2[ai*68 + cj] = acc[mt][nt][e];
                        }
                    }
            }
        }
        __syncthreads();

        if (j0 + 64 < SS && tid < 256) {
            const uint32_t* kn32 = k32 + (size_t)(j0 + 64) * 32;
            const int basen = i0 - (j0 + 64) + 449;
#pragma unroll
            for (int i = 0; i < 2; i++) {
                const int u = tid + i*256, row = u >> 3, c = u & 7;
                cp16(smKs + (uint32_t)(row*144 + c*16), kn32 + row*32 + c*4);
            }
#pragma unroll
            for (int i = 0; i < 4; i++) {
                const int u = tid + i*256, pr = u >> 3, c = u & 7;
                int grow = basen + pr;
                grow = grow < 0 ? 0 : (grow > 1023 ? 1023 : grow);
                cp16(smPs + (uint32_t)(pr*144 + c*16), p32 + grow*32 + c*4);
            }
            CP_COMMIT();
        }

        if (tid < 256) {
            const int row = tid >> 2, q4 = tid & 3;
            const int c0 = q4*16;
            float v[16];
            float mloc = -1e30f;
#pragma unroll
            for (int i4 = 0; i4 < 4; i4++) {
                const float4 sc = *(const float4*)&SsF[row*68 + c0 + 4*i4];
                const float4 y2 = *(const float4*)&B2[row*68 + c0 + 4*i4];
                const float4 y1 = *(const float4*)&B1[row*68 + c0 + 4*i4];
                const float4 mk = *(const float4*)&sm_mask[j0 + c0 + 4*i4];
                v[4*i4+0] = (sc.x + y2.x + 0.125f*y1.x) * s1 + mk.x;
                v[4*i4+1] = (sc.y + y2.y + 0.125f*y1.y) * s1 + mk.y;
                v[4*i4+2] = (sc.z + y2.z + 0.125f*y1.z) * s1 + mk.z;
                v[4*i4+3] = (sc.w + y2.w + 0.125f*y1.w) * s1 + mk.w;
                mloc = fmaxf(mloc, fmaxf(fmaxf(v[4*i4], v[4*i4+1]), fmaxf(v[4*i4+2], v[4*i4+3])));
            }
            mloc = fmaxf(mloc, __shfl_xor_sync(0xffffffffu, mloc, 1));
            mloc = fmaxf(mloc, __shfl_xor_sync(0xffffffffu, mloc, 2));
            const float mold = sm_m[row];
            const float mnew = fmaxf(mold, mloc);
            float lsum = 0.f;
#pragma unroll
            for (int i = 0; i < 8; i++) {
                const float e0 = __expf(v[2*i]   - mnew);
                const float e1 = __expf(v[2*i+1] - mnew);
                Pt2[row*36 + q4*8 + i] = packh2(e0, e1);
                lsum += e0 + e1;
            }
            lsum += __shfl_xor_sync(0xffffffffu, lsum, 1);
            lsum += __shfl_xor_sync(0xffffffffu, lsum, 2);
            if (q4 == 0) {
                const float sc = __expf(mold - mnew);
                sm_m[row] = mnew;
                sm_scale[row] = sc;
                sm_l[row] = sm_l[row] * sc + lsum;
            }
            if (j0 + 64 < SS) { CP_WAIT1(); } else { CP_WAIT0(); }
        }
        __syncthreads();

        if (wid < 8) {
            const float sc0 = sm_scale[wm*16 + g];
            const float sc1 = sm_scale[wm*16 + g + 8];
#pragma unroll
            for (int nt = 0; nt < 4; nt++) {
                acc_o[nt][0] *= sc0; acc_o[nt][1] *= sc0;
                acc_o[nt][2] *= sc1; acc_o[nt][3] *= sc1;
            }
#pragma unroll
            for (int ks = 0; ks < 4; ks++) {
                uint32_t a[4], b[4][2];
                ldm_x4(a[0], a[1], a[2], a[3], aPV + (uint32_t)(ks*32));
#pragma unroll
                for (int ntp = 0; ntp < 2; ntp++)
                    ldm_x4_t(b[2*ntp][0], b[2*ntp][1], b[2*ntp+1][0], b[2*ntp+1][1],
                             bPVt + (uint32_t)(ks*16*144 + ntp*32));
#pragma unroll
                for (int nt = 0; nt < 4; nt++)
                    mma_f16(acc_o[nt], a, b[nt]);
            }
        }
    }
    __syncthreads();

    if (wid < 8) {
        const int r0 = wm*16 + g;
        const float inv0 = 1.f / sm_l[r0];
        const float inv1 = 1.f / sm_l[r0 + 8];
#pragma unroll
        for (int nt = 0; nt < 4; nt++) {
            const int col = wn*32 + nt*8 + 2*t;
            const size_t o0 = ((size_t)b_*SS + i0 + r0)*HIDN + h*DD + col;
            const size_t o1 = ((size_t)b_*SS + i0 + r0 + 8)*HIDN + h*DD + col;
            *(float2*)(out + o0) = make_float2(acc_o[nt][0]*inv0, acc_o[nt][1]*inv0);
            *(float2*)(out + o1) = make_float2(acc_o[nt][2]*inv1, acc_o[nt][3]*inv1);
        }
    }
}

// ---------------- launch ---------------------------------------------------
extern "C" void kernel_launch(void* const* d_in, const int* in_sizes, int n_in,
                              void* d_out, int out_size)
{
    const float* hs  = (const float*)d_in[0];
    const float* msk = (const float*)d_in[1];
    const float* Wq  = (const float*)d_in[3];
    const float* bq  = (const float*)d_in[4];
    const float* Wk  = (const float*)d_in[5];
    const float* bk  = (const float*)d_in[6];
    const float* Wv  = (const float*)d_in[7];
    const float* bv  = (const float*)d_in[8];
    const float* Wpk = (const float*)d_in[9];
    const float* bpk = (const float*)d_in[10];
    const float* rel = (const float*)d_in[11];
    float* out = (float*)d_out;

    cudaFuncSetAttribute(gemm_tc, cudaFuncAttributeMaxDynamicSharedMemorySize, GEMM_SMEM);
    cudaFuncSetAttribute(flash_tc, cudaFuncAttributeMaxDynamicSharedMemorySize, FL_SMEM);

    dim3 gc(2048, 6);                     // fp32 -> fp16 one-time convert (32B/thr)
    precvt<<<gc, 256>>>(hs, rel, Wq, Wk, Wv, Wpk);

    dim3 gg(8, 32, 4);                    // z: Wq, Wk, Wv, Wpk (y>=8 idles for z=3)
    gemm_tc<<<gg, 256, GEMM_SMEM>>>(bq, bk, bv, bpk);

    dim3 gf(SS/64, BH);                   // (8, 128)
    flash_tc<<<gf, 320, FL_SMEM>>>(msk, out);
}

// round 16
// speedup vs baseline: 1.0330x; 1.0330x over previous
#include <cuda_runtime.h>
#include <cuda_fp16.h>
#include <cstdint>

#define BB   8
#define SS   512
#define HH   16
#define DD   64
#define HIDN 1024
#define BH   (BB*HH)   // 128

// ---------------- scratch (device globals, fp16 packed as half2 words) -----
__device__ uint32_t g_q[BH*SS*DD/2];            // [b,h,s,d/2] 8MB
__device__ uint32_t g_k[BH*SS*DD/2];
__device__ uint32_t g_v[BH*SS*DD/2];
__device__ uint32_t g_pos[HH*1024*DD/2];        // [h,p,d/2]   2MB
__device__ uint32_t g_hs16[BB*SS*HIDN/2];       // fp16 hidden_states 8MB
__device__ uint32_t g_rel16[1024*HIDN/2];       // fp16 rel_emb 2MB
__device__ uint32_t g_w16[4][HIDN*HIDN/2];      // fp16 Wq,Wk,Wv,Wpk 4x2MB

// ---------------- helpers ---------------------------------------------------
__device__ __forceinline__ uint32_t packh2(float lo, float hi) {
    uint32_t u;
    asm("cvt.rn.f16x2.f32 %0, %1, %2;" : "=r"(u) : "f"(hi), "f"(lo));
    return u;
}
__device__ __forceinline__ uint32_t smaddr(const void* p) {
    uint32_t a;
    asm("{ .reg .u64 t; cvta.to.shared.u64 t, %1; cvt.u32.u64 %0, t; }" : "=r"(a) : "l"(p));
    return a;
}
__device__ __forceinline__ void mma_f16(float c[4], const uint32_t a[4], const uint32_t b[2]) {
    asm volatile("mma.sync.aligned.m16n8k16.row.col.f32.f16.f16.f32 "
        "{%0,%1,%2,%3}, {%4,%5,%6,%7}, {%8,%9}, {%0,%1,%2,%3};"
        : "+f"(c[0]), "+f"(c[1]), "+f"(c[2]), "+f"(c[3])
        : "r"(a[0]), "r"(a[1]), "r"(a[2]), "r"(a[3]), "r"(b[0]), "r"(b[1]));
}
__device__ __forceinline__ void ldm_x4(uint32_t& r0, uint32_t& r1, uint32_t& r2, uint32_t& r3,
                                       uint32_t addr) {
    asm volatile("ldmatrix.sync.aligned.m8n8.x4.shared.b16 {%0,%1,%2,%3}, [%4];"
        : "=r"(r0), "=r"(r1), "=r"(r2), "=r"(r3) : "r"(addr));
}
__device__ __forceinline__ void ldm_x4_t(uint32_t& r0, uint32_t& r1, uint32_t& r2, uint32_t& r3,
                                         uint32_t addr) {
    asm volatile("ldmatrix.sync.aligned.m8n8.x4.trans.shared.b16 {%0,%1,%2,%3}, [%4];"
        : "=r"(r0), "=r"(r1), "=r"(r2), "=r"(r3) : "r"(addr));
}
__device__ __forceinline__ void cp16(uint32_t smem_dst, const void* gsrc) {
    asm volatile("cp.async.ca.shared.global [%0], [%1], 16;" :: "r"(smem_dst), "l"(gsrc));
}
#define CP_COMMIT() asm volatile("cp.async.commit_group;" ::: "memory")
#define CP_WAIT0()  asm volatile("cp.async.wait_group 0;" ::: "memory")
#define CP_WAIT1()  asm volatile("cp.async.wait_group 1;" ::: "memory")

// fragment-base lane offsets
#define A_ROW(lane)  ((lane) & 15)
#define A_COL(lane)  ((((lane) >> 4) & 1) << 2)
#define B_ROW(lane)  (((((lane) >> 4) & 1) << 3) + ((lane) & 7))
#define B_COL(lane)  ((((lane) >> 3) & 1) << 2)

// ---------------- precvt: fp32 -> fp16 (one-time, 64B/thread) ---------------
__global__ __launch_bounds__(256) void precvt(
    const float* __restrict__ hs, const float* __restrict__ rel,
    const float* __restrict__ Wq, const float* __restrict__ Wk,
    const float* __restrict__ Wv, const float* __restrict__ Wpk)
{
    const int seg = blockIdx.y;
    const float* src;
    uint32_t* dst;
    int n;
    switch (seg) {
        case 0: src = hs;  dst = g_hs16;  n = BB*SS*HIDN; break;
        case 1: src = rel; dst = g_rel16; n = 1024*HIDN;  break;
        case 2: src = Wq;  dst = g_w16[0]; n = HIDN*HIDN; break;
        case 3: src = Wk;  dst = g_w16[1]; n = HIDN*HIDN; break;
        case 4: src = Wv;  dst = g_w16[2]; n = HIDN*HIDN; break;
        default: src = Wpk; dst = g_w16[3]; n = HIDN*HIDN; break;
    }
    const int i = (blockIdx.x * 256 + threadIdx.x) * 16;
    if (i >= n) return;
    const float4 x0 = *(const float4*)(src + i);
    const float4 x1 = *(const float4*)(src + i + 4);
    const float4 x2 = *(const float4*)(src + i + 8);
    const float4 x3 = *(const float4*)(src + i + 12);
    *(uint4*)&dst[(i >> 1)]     = make_uint4(packh2(x0.x, x0.y), packh2(x0.z, x0.w),
                                             packh2(x1.x, x1.y), packh2(x1.z, x1.w));
    *(uint4*)&dst[(i >> 1) + 4] = make_uint4(packh2(x2.x, x2.y), packh2(x2.z, x2.w),
                                             packh2(x3.x, x3.y), packh2(x3.z, x3.w));
}

// ---------------- fp16 HMMA projection GEMM (R14: K-chunk 64, 2-buf) -------
__global__ __launch_bounds__(256, 2) void gemm_tc(
    const float* __restrict__ bq, const float* __restrict__ bk,
    const float* __restrict__ bv, const float* __restrict__ bpk)
{
    __shared__ uint32_t sm[2*9216];   // [A0|B0|A1|B1], each 128x36 words

    const int which = blockIdx.z;
    if (which == 3 && blockIdx.y >= 8) return;

    const uint32_t* Ag = ((which == 3) ? g_rel16 : g_hs16);
    const uint32_t* Bg = g_w16[which];
    const float* bias = (which == 0) ? bq : (which == 1) ? bk : (which == 2) ? bv : bpk;
    uint32_t* outp    = (which == 0) ? g_q : (which == 1) ? g_k : (which == 2) ? g_v : g_pos;

    const int bm = blockIdx.y * 128;
    const int bn = blockIdx.x * 128;
    const int tid = threadIdx.x;
    const int wid = tid >> 5, lane = tid & 31;
    const int wm = wid >> 1, wn = wid & 1;
    const int g = lane >> 2, t = lane & 3;

    Ag += (size_t)bm * (HIDN/2);
    Bg += (size_t)bn * (HIDN/2);

    float acc[2][8][4];
#pragma unroll
    for (int mt = 0; mt < 2; mt++)
#pragma unroll
        for (int nt = 0; nt < 8; nt++)
#pragma unroll
            for (int i = 0; i < 4; i++) acc[mt][nt][i] = 0.f;

    const uint32_t smBase = smaddr(sm);
    const uint32_t aFB = smaddr(&sm[(wm*32 + A_ROW(lane))*36 + A_COL(lane)]);
    const uint32_t bFB = smaddr(&sm[4608 + (wn*64 + B_ROW(lane))*36 + B_COL(lane)]);

#pragma unroll
    for (int i = 0; i < 4; i++) {
        const int u = tid + i*256, row = u >> 3, c = u & 7;
        cp16(smBase + (uint32_t)(row*144 + c*16),          Ag + (size_t)row*512 + c*4);
        cp16(smBase + (uint32_t)(4608*4 + row*144 + c*16), Bg + (size_t)row*512 + c*4);
    }
    CP_COMMIT();

    for (int kc = 0; kc < 16; kc++) {
        const int cur = kc & 1;
        if (kc < 15) {
            const uint32_t off = (uint32_t)((cur ^ 1) * 9216 * 4);
            const int kk = (kc + 1) * 32;
#pragma unroll
            for (int i = 0; i < 4; i++) {
                const int u = tid + i*256, row = u >> 3, c = u & 7;
                cp16(smBase + off + (uint32_t)(row*144 + c*16),          Ag + (size_t)row*512 + kk + c*4);
                cp16(smBase + off + (uint32_t)(4608*4 + row*144 + c*16), Bg + (size_t)row*512 + kk + c*4);
            }
            CP_COMMIT();
            CP_WAIT1();
        } else {
            CP_WAIT0();
        }
        __syncthreads();

        const uint32_t boff = (uint32_t)(cur * 9216 * 4);
#pragma unroll
        for (int ks = 0; ks < 4; ks++) {
            uint32_t a[2][4], b[8][2];
#pragma unroll
            for (int mt = 0; mt < 2; mt++)
                ldm_x4(a[mt][0], a[mt][1], a[mt][2], a[mt][3],
                       aFB + boff + (uint32_t)(mt*16*36*4 + ks*32));
#pragma unroll
            for (int ntp = 0; ntp < 4; ntp++)
                ldm_x4(b[2*ntp][0], b[2*ntp][1], b[2*ntp+1][0], b[2*ntp+1][1],
                       bFB + boff + (uint32_t)(ntp*16*36*4 + ks*32));
#pragma unroll
            for (int mt = 0; mt < 2; mt++)
#pragma unroll
                for (int nt = 0; nt < 8; nt++)
                    mma_f16(acc[mt][nt], a[mt], b[nt]);
        }
        __syncthreads();
    }

#pragma unroll
    for (int mt = 0; mt < 2; mt++) {
#pragma unroll
        for (int nt = 0; nt < 8; nt++) {
            const int n = bn + wn*64 + nt*8 + 2*t;
            const float bv0 = bias[n], bv1 = bias[n+1];
#pragma unroll
            for (int half = 0; half < 2; half++) {
                const int m = bm + wm*32 + mt*16 + g + half*8;
                const float v0 = acc[mt][nt][half*2+0] + bv0;
                const float v1 = acc[mt][nt][half*2+1] + bv1;
                size_t oi;
                if (which < 3) {
                    const int b_ = m >> 9, s = m & 511, h = n >> 6, d = n & 63;
                    oi = (((size_t)(b_*HH + h))*SS + s)*DD + d;
                } else {
                    oi = (((size_t)(n >> 6))*1024 + m)*DD + (n & 63);
                }
                outp[oi >> 1] = packh2(v0, v1);
            }
        }
    }
}

// ---------------- fused flash kernel (R14: fully pipelined cp.async) -------
#define FL_SMEM (27584 * 4)   // x2 = 220672 <= 228KB/SM

__global__ __launch_bounds__(320, 2) void flash_tc(const float* __restrict__ mask,
                                                   float* __restrict__ out)
{
    extern __shared__ uint32_t smw[];
    uint32_t* Qs  = smw;                    // [64 i][36 w]
    uint32_t* Ks  = smw + 2304;             // [64 j][36 w]
    uint32_t* Ps  = smw + 4608;             // [128 p][36 w]
    uint32_t* Vs  = smw + 9216;             // [64 j][36 w] row-major V
    uint32_t* Pt2 = smw + 11520;            // [64 i][36 w] P~ f16
    float*    SsF = (float*)(smw + 13824);  // [64][68] CC
    float*    B1  = (float*)(smw + 18176);  // [64][68] sheared CPF
    float*    B2  = (float*)(smw + 22528);  // [64][68] sheared PCF
    float* sm_m     = (float*)(smw + 26880);
    float* sm_l     = sm_m + 64;
    float* sm_scale = sm_m + 128;
    float* sm_mask  = sm_m + 192;           // [512] full mask row

    const int i0 = blockIdx.x * 64;
    const int bh = blockIdx.y;
    const int b_ = bh >> 4, h = bh & 15;
    const int tid = threadIdx.x;
    const int wid = tid >> 5, lane = tid & 31;
    const int g = lane >> 2, t = lane & 3;
    const int wm = wid >> 1, wn = wid & 1;

    const uint32_t* q32 = g_q + ((size_t)bh*SS + i0) * (DD/2);
    const uint32_t* k32 = g_k + (size_t)bh*SS*(DD/2);
    const uint32_t* v32 = g_v + (size_t)bh*SS*(DD/2);
    const uint32_t* p32 = g_pos + (size_t)h * 1024 * (DD/2);

    const uint32_t smQs = smaddr(Qs), smKs = smaddr(Ks), smPs = smaddr(Ps), smVs = smaddr(Vs);

    for (int u = tid; u < 512; u += 320)
        sm_mask[u] = mask[(size_t)b_*SS + u];
    if (tid < 256) {
#pragma unroll
        for (int i = 0; i < 2; i++) {
            const int u = tid + i*256, row = u >> 3, c = u & 7;
            cp16(smQs + (uint32_t)(row*144 + c*16), q32 + row*32 + c*4);
            cp16(smKs + (uint32_t)(row*144 + c*16), k32 + row*32 + c*4);
        }
        const int base0 = i0 + 449;
#pragma unroll
        for (int i = 0; i < 4; i++) {
            const int u = tid + i*256, pr = u >> 3, c = u & 7;
            int grow = base0 + pr;
            grow = grow < 0 ? 0 : (grow > 1023 ? 1023 : grow);
            cp16(smPs + (uint32_t)(pr*144 + c*16), p32 + grow*32 + c*4);
        }
        CP_COMMIT();
    }
    if (tid < 64) { sm_m[tid] = -1e30f; sm_l[tid] = 0.f; }

    float acc_o[4][4];
#pragma unroll
    for (int nt = 0; nt < 4; nt++)
#pragma unroll
        for (int e = 0; e < 4; e++) acc_o[nt][e] = 0.f;

    const uint32_t* Ap; const uint32_t* Bp;
    int Arow, Brow;
    int kind;
    if (wid < 2)      { Ap = Qs; Arow = wid*32;          Bp = Ks; Brow = 0;                 kind = 0; }
    else if (wid < 6) { Ap = Qs; Arow = ((wid-2)&1)*32;  Bp = Ps; Brow = ((wid-2)>>1)*64;   kind = 1; }
    else              { Ap = Ps; Arow = (wid-6)*32;      Bp = Ks; Brow = 0;                 kind = 2; }

    const uint32_t aFB = smaddr(&Ap[(Arow + A_ROW(lane))*36 + A_COL(lane)]);
    const uint32_t bFB = smaddr(&Bp[(Brow + B_ROW(lane))*36 + B_COL(lane)]);
    const uint32_t aPV = smaddr(&Pt2[(wm*16 + A_ROW(lane))*36 + A_COL(lane)]);
    const uint32_t bPVt = smVs
        + (uint32_t)((((lane >> 3) & 1) * 8 + (lane & 7)) * 144
                     + ((lane >> 4) & 1) * 16 + wn * 64);

    const float s1 = 0.14433756729740643f;      // 1/sqrt(48)

    for (int j0 = 0; j0 < SS; j0 += 64) {
        __syncthreads();

        if (tid < 256) {
            const uint32_t* vc32 = v32 + (size_t)j0 * 32;
#pragma unroll
            for (int i = 0; i < 2; i++) {
                const int u = tid + i*256, row = u >> 3, c = u & 7;
                cp16(smVs + (uint32_t)(row*144 + c*16), vc32 + row*32 + c*4);
            }
            CP_COMMIT();
            CP_WAIT1();    // drain K/P_cur; V_cur stays in flight
        }
        __syncthreads();

#pragma unroll
        for (int hN = 0; hN < 2; hN++) {
            float acc[2][4][4];
#pragma unroll
            for (int mt = 0; mt < 2; mt++)
#pragma unroll
                for (int nt = 0; nt < 4; nt++)
#pragma unroll
                    for (int e = 0; e < 4; e++) acc[mt][nt][e] = 0.f;

#pragma unroll
            for (int ks = 0; ks < 4; ks++) {
                uint32_t a[2][4], b[4][2];
#pragma unroll
                for (int mt = 0; mt < 2; mt++)
                    ldm_x4(a[mt][0], a[mt][1], a[mt][2], a[mt][3],
                           aFB + (uint32_t)(mt*16*36*4 + ks*32));
#pragma unroll
                for (int ntp = 0; ntp < 2; ntp++)
                    ldm_x4(b[2*ntp][0], b[2*ntp][1], b[2*ntp+1][0], b[2*ntp+1][1],
                           bFB + (uint32_t)((hN*32 + ntp*16)*36*4 + ks*32));
#pragma unroll
                for (int mt = 0; mt < 2; mt++)
#pragma unroll
                    for (int nt = 0; nt < 4; nt++)
                        mma_f16(acc[mt][nt], a[mt], b[nt]);
            }

            if (kind == 0) {
#pragma unroll
                for (int mt = 0; mt < 2; mt++)
#pragma unroll
                    for (int nt = 0; nt < 4; nt++) {
                        const int r0 = Arow + mt*16 + g;
                        const int c0 = (hN*4 + nt)*8 + 2*t;
                        *(float2*)&SsF[r0*68 + c0]     = make_float2(acc[mt][nt][0], acc[mt][nt][1]);
                        *(float2*)&SsF[(r0+8)*68 + c0] = make_float2(acc[mt][nt][2], acc[mt][nt][3]);
                    }
            } else if (kind == 1) {
#pragma unroll
                for (int mt = 0; mt < 2; mt++)
#pragma unroll
                    for (int nt = 0; nt < 4; nt++) {
                        const int ai0 = Arow + mt*16 + g;
                        const int p0 = Brow + (hN*4 + nt)*8 + 2*t;
#pragma unroll
                        for (int e = 0; e < 4; e++) {
                            const int ai = ai0 + (e >> 1)*8;
                            const int p  = p0 + (e & 1);
                            const int cj = ai - p + 63;
                            if ((unsigned)cj < 64u)
                                B1[ai*68 + cj] = acc[mt][nt][e];
                        }
                    }
            } else {
#pragma unroll
                for (int mt = 0; mt < 2; mt++)
#pragma unroll
                    for (int nt = 0; nt < 4; nt++) {
                        const int r0 = Arow + mt*16 + g;
                        const int c0 = (hN*4 + nt)*8 + 2*t;
#pragma unroll
                        for (int e = 0; e < 4; e++) {
                            const int r  = r0 + (e >> 1)*8;
                            const int cj = c0 + (e & 1);
                            const int ai = r + cj - 63;
                            if ((unsigned)ai < 64u)
                                B2[ai*68 + cj] = acc[mt][nt][e];
                        }
                    }
            }
        }
        __syncthreads();

        if (j0 + 64 < SS && tid < 256) {
            const uint32_t* kn32 = k32 + (size_t)(j0 + 64) * 32;
            const int basen = i0 - (j0 + 64) + 449;
#pragma unroll
            for (int i = 0; i < 2; i++) {
                const int u = tid + i*256, row = u >> 3, c = u & 7;
                cp16(smKs + (uint32_t)(row*144 + c*16), kn32 + row*32 + c*4);
            }
#pragma unroll
            for (int i = 0; i < 4; i++) {
                const int u = tid + i*256, pr = u >> 3, c = u & 7;
                int grow = basen + pr;
                grow = grow < 0 ? 0 : (grow > 1023 ? 1023 : grow);
                cp16(smPs + (uint32_t)(pr*144 + c*16), p32 + grow*32 + c*4);
            }
            CP_COMMIT();
        }

        if (tid < 256) {
            const int row = tid >> 2, q4 = tid & 3;
            const int c0 = q4*16;
            float v[16];
            float mloc = -1e30f;
#pragma unroll
            for (int i4 = 0; i4 < 4; i4++) {
                const float4 sc = *(const float4*)&SsF[row*68 + c0 + 4*i4];
                const float4 y2 = *(const float4*)&B2[row*68 + c0 + 4*i4];
                const float4 y1 = *(const float4*)&B1[row*68 + c0 + 4*i4];
                const float4 mk = *(const float4*)&sm_mask[j0 + c0 + 4*i4];
                v[4*i4+0] = (sc.x + y2.x + 0.125f*y1.x) * s1 + mk.x;
                v[4*i4+1] = (sc.y + y2.y + 0.125f*y1.y) * s1 + mk.y;
                v[4*i4+2] = (sc.z + y2.z + 0.125f*y1.z) * s1 + mk.z;
                v[4*i4+3] = (sc.w + y2.w + 0.125f*y1.w) * s1 + mk.w;
                mloc = fmaxf(mloc, fmaxf(fmaxf(v[4*i4], v[4*i4+1]), fmaxf(v[4*i4+2], v[4*i4+3])));
            }
            mloc = fmaxf(mloc, __shfl_xor_sync(0xffffffffu, mloc, 1));
            mloc = fmaxf(mloc, __shfl_xor_sync(0xffffffffu, mloc, 2));
            const float mold = sm_m[row];
            const float mnew = fmaxf(mold, mloc);
            float lsum = 0.f;
#pragma unroll
            for (int i = 0; i < 8; i++) {
                const float e0 = __expf(v[2*i]   - mnew);
                const float e1 = __expf(v[2*i+1] - mnew);
                Pt2[row*36 + q4*8 + i] = packh2(e0, e1);
                lsum += e0 + e1;
            }
            lsum += __shfl_xor_sync(0xffffffffu, lsum, 1);
            lsum += __shfl_xor_sync(0xffffffffu, lsum, 2);
            if (q4 == 0) {
                const float sc = __expf(mold - mnew);
                sm_m[row] = mnew;
                sm_scale[row] = sc;
                sm_l[row] = sm_l[row] * sc + lsum;
            }
            if (j0 + 64 < SS) { CP_WAIT1(); } else { CP_WAIT0(); }
        }
        __syncthreads();

        if (wid < 8) {
            const float sc0 = sm_scale[wm*16 + g];
            const float sc1 = sm_scale[wm*16 + g + 8];
#pragma unroll
            for (int nt = 0; nt < 4; nt++) {
                acc_o[nt][0] *= sc0; acc_o[nt][1] *= sc0;
                acc_o[nt][2] *= sc1; acc_o[nt][3] *= sc1;
            }
#pragma unroll
            for (int ks = 0; ks < 4; ks++) {
                uint32_t a[4], b[4][2];
                ldm_x4(a[0], a[1], a[2], a[3], aPV + (uint32_t)(ks*32));
#pragma unroll
                for (int ntp = 0; ntp < 2; ntp++)
                    ldm_x4_t(b[2*ntp][0], b[2*ntp][1], b[2*ntp+1][0], b[2*ntp+1][1],
                             bPVt + (uint32_t)(ks*16*144 + ntp*32));
#pragma unroll
                for (int nt = 0; nt < 4; nt++)
                    mma_f16(acc_o[nt], a, b[nt]);
            }
        }
    }
    __syncthreads();

    if (wid < 8) {
        const int r0 = wm*16 + g;
        const float inv0 = 1.f / sm_l[r0];
        const float inv1 = 1.f / sm_l[r0 + 8];
#pragma unroll
        for (int nt = 0; nt < 4; nt++) {
            const int col = wn*32 + nt*8 + 2*t;
            const size_t o0 = ((size_t)b_*SS + i0 + r0)*HIDN + h*DD + col;
            const size_t o1 = ((size_t)b_*SS + i0 + r0 + 8)*HIDN + h*DD + col;
            *(float2*)(out + o0) = make_float2(acc_o[nt][0]*inv0, acc_o[nt][1]*inv0);
            *(float2*)(out + o1) = make_float2(acc_o[nt][2]*inv1, acc_o[nt][3]*inv1);
        }
    }
}

// ---------------- launch ---------------------------------------------------
extern "C" void kernel_launch(void* const* d_in, const int* in_sizes, int n_in,
                              void* d_out, int out_size)
{
    const float* hs  = (const float*)d_in[0];
    const float* msk = (const float*)d_in[1];
    const float* Wq  = (const float*)d_in[3];
    const float* bq  = (const float*)d_in[4];
    const float* Wk  = (const float*)d_in[5];
    const float* bk  = (const float*)d_in[6];
    const float* Wv  = (const float*)d_in[7];
    const float* bv  = (const float*)d_in[8];
    const float* Wpk = (const float*)d_in[9];
    const float* bpk = (const float*)d_in[10];
    const float* rel = (const float*)d_in[11];
    float* out = (float*)d_out;

    cudaFuncSetAttribute(flash_tc, cudaFuncAttributeMaxDynamicSharedMemorySize, FL_SMEM);

    dim3 gc(1024, 6);                     // fp32 -> fp16 one-time convert (64B/thr)
    precvt<<<gc, 256>>>(hs, rel, Wq, Wk, Wv, Wpk);

    dim3 gg(8, 32, 4);                    // z: Wq, Wk, Wv, Wpk (y>=8 idles for z=3)
    gemm_tc<<<gg, 256>>>(bq, bk, bv, bpk);

    dim3 gf(SS/64, BH);                   // (8, 128)
    flash_tc<<<gf, 320, FL_SMEM>>>(msk, out);
}

// round 17
// speedup vs baseline: 1.0358x; 1.0026x over previous
#include <cuda_runtime.h>
#include <cuda_fp16.h>
#include <cstdint>

#define BB   8
#define SS   512
#define HH   16
#define DD   64
#define HIDN 1024
#define BH   (BB*HH)   // 128

// ---------------- scratch (device globals, fp16 packed as half2 words) -----
__device__ uint32_t g_q[BH*SS*DD/2];            // [b,h,s,d/2] 8MB
__device__ uint32_t g_k[BH*SS*DD/2];
__device__ uint32_t g_v[BH*SS*DD/2];
__device__ uint32_t g_pos[HH*1024*DD/2];        // [h,p,d/2]   2MB
__device__ uint32_t g_hs16[BB*SS*HIDN/2];       // fp16 hidden_states 8MB
__device__ uint32_t g_rel16[1024*HIDN/2];       // fp16 rel_emb 2MB
__device__ uint32_t g_w16[4][HIDN*HIDN/2];      // fp16 Wq,Wk,Wv,Wpk 4x2MB

// ---------------- helpers ---------------------------------------------------
__device__ __forceinline__ uint32_t packh2(float lo, float hi) {
    uint32_t u;
    asm("cvt.rn.f16x2.f32 %0, %1, %2;" : "=r"(u) : "f"(hi), "f"(lo));
    return u;
}
__device__ __forceinline__ uint32_t smaddr(const void* p) {
    uint32_t a;
    asm("{ .reg .u64 t; cvta.to.shared.u64 t, %1; cvt.u32.u64 %0, t; }" : "=r"(a) : "l"(p));
    return a;
}
__device__ __forceinline__ void mma_f16(float c[4], const uint32_t a[4], const uint32_t b[2]) {
    asm volatile("mma.sync.aligned.m16n8k16.row.col.f32.f16.f16.f32 "
        "{%0,%1,%2,%3}, {%4,%5,%6,%7}, {%8,%9}, {%0,%1,%2,%3};"
        : "+f"(c[0]), "+f"(c[1]), "+f"(c[2]), "+f"(c[3])
        : "r"(a[0]), "r"(a[1]), "r"(a[2]), "r"(a[3]), "r"(b[0]), "r"(b[1]));
}
__device__ __forceinline__ void ldm_x4(uint32_t& r0, uint32_t& r1, uint32_t& r2, uint32_t& r3,
                                       uint32_t addr) {
    asm volatile("ldmatrix.sync.aligned.m8n8.x4.shared.b16 {%0,%1,%2,%3}, [%4];"
        : "=r"(r0), "=r"(r1), "=r"(r2), "=r"(r3) : "r"(addr));
}
__device__ __forceinline__ void ldm_x4_t(uint32_t& r0, uint32_t& r1, uint32_t& r2, uint32_t& r3,
                                         uint32_t addr) {
    asm volatile("ldmatrix.sync.aligned.m8n8.x4.trans.shared.b16 {%0,%1,%2,%3}, [%4];"
        : "=r"(r0), "=r"(r1), "=r"(r2), "=r"(r3) : "r"(addr));
}
__device__ __forceinline__ void cp16(uint32_t smem_dst, const void* gsrc) {
    asm volatile("cp.async.ca.shared.global [%0], [%1], 16;" :: "r"(smem_dst), "l"(gsrc));
}
#define CP_COMMIT() asm volatile("cp.async.commit_group;" ::: "memory")
#define CP_WAIT0()  asm volatile("cp.async.wait_group 0;" ::: "memory")
#define CP_WAIT1()  asm volatile("cp.async.wait_group 1;" ::: "memory")

// fragment-base lane offsets
#define A_ROW(lane)  ((lane) & 15)
#define A_COL(lane)  ((((lane) >> 4) & 1) << 2)
#define B_ROW(lane)  (((((lane) >> 4) & 1) << 3) + ((lane) & 7))
#define B_COL(lane)  ((((lane) >> 3) & 1) << 2)

// ---------------- precvt: fp32 -> fp16 (one-time, 64B/thread) ---------------
__global__ __launch_bounds__(256) void precvt(
    const float* __restrict__ hs, const float* __restrict__ rel,
    const float* __restrict__ Wq, const float* __restrict__ Wk,
    const float* __restrict__ Wv, const float* __restrict__ Wpk)
{
    const int seg = blockIdx.y;
    const float* src;
    uint32_t* dst;
    int n;
    switch (seg) {
        case 0: src = hs;  dst = g_hs16;  n = BB*SS*HIDN; break;
        case 1: src = rel; dst = g_rel16; n = 1024*HIDN;  break;
        case 2: src = Wq;  dst = g_w16[0]; n = HIDN*HIDN; break;
        case 3: src = Wk;  dst = g_w16[1]; n = HIDN*HIDN; break;
        case 4: src = Wv;  dst = g_w16[2]; n = HIDN*HIDN; break;
        default: src = Wpk; dst = g_w16[3]; n = HIDN*HIDN; break;
    }
    const int i = (blockIdx.x * 256 + threadIdx.x) * 16;
    if (i >= n) return;
    const float4 x0 = *(const float4*)(src + i);
    const float4 x1 = *(const float4*)(src + i + 4);
    const float4 x2 = *(const float4*)(src + i + 8);
    const float4 x3 = *(const float4*)(src + i + 12);
    *(uint4*)&dst[(i >> 1)]     = make_uint4(packh2(x0.x, x0.y), packh2(x0.z, x0.w),
                                             packh2(x1.x, x1.y), packh2(x1.z, x1.w));
    *(uint4*)&dst[(i >> 1) + 4] = make_uint4(packh2(x2.x, x2.y), packh2(x2.z, x2.w),
                                             packh2(x3.x, x3.y), packh2(x3.z, x3.w));
}

// ---------------- fp16 HMMA projection GEMM (R14: K-chunk 64, 2-buf) -------
__global__ __launch_bounds__(256, 2) void gemm_tc(
    const float* __restrict__ bq, const float* __restrict__ bk,
    const float* __restrict__ bv, const float* __restrict__ bpk)
{
    __shared__ uint32_t sm[2*9216];   // [A0|B0|A1|B1], each 128x36 words

    const int which = blockIdx.z;
    if (which == 3 && blockIdx.y >= 8) return;

    const uint32_t* Ag = ((which == 3) ? g_rel16 : g_hs16);
    const uint32_t* Bg = g_w16[which];
    const float* bias = (which == 0) ? bq : (which == 1) ? bk : (which == 2) ? bv : bpk;
    uint32_t* outp    = (which == 0) ? g_q : (which == 1) ? g_k : (which == 2) ? g_v : g_pos;

    const int bm = blockIdx.y * 128;
    const int bn = blockIdx.x * 128;
    const int tid = threadIdx.x;
    const int wid = tid >> 5, lane = tid & 31;
    const int wm = wid >> 1, wn = wid & 1;
    const int g = lane >> 2, t = lane & 3;

    Ag += (size_t)bm * (HIDN/2);
    Bg += (size_t)bn * (HIDN/2);

    float acc[2][8][4];
#pragma unroll
    for (int mt = 0; mt < 2; mt++)
#pragma unroll
        for (int nt = 0; nt < 8; nt++)
#pragma unroll
            for (int i = 0; i < 4; i++) acc[mt][nt][i] = 0.f;

    const uint32_t smBase = smaddr(sm);
    const uint32_t aFB = smaddr(&sm[(wm*32 + A_ROW(lane))*36 + A_COL(lane)]);
    const uint32_t bFB = smaddr(&sm[4608 + (wn*64 + B_ROW(lane))*36 + B_COL(lane)]);

#pragma unroll
    for (int i = 0; i < 4; i++) {
        const int u = tid + i*256, row = u >> 3, c = u & 7;
        cp16(smBase + (uint32_t)(row*144 + c*16),          Ag + (size_t)row*512 + c*4);
        cp16(smBase + (uint32_t)(4608*4 + row*144 + c*16), Bg + (size_t)row*512 + c*4);
    }
    CP_COMMIT();

    for (int kc = 0; kc < 16; kc++) {
        const int cur = kc & 1;
        if (kc < 15) {
            const uint32_t off = (uint32_t)((cur ^ 1) * 9216 * 4);
            const int kk = (kc + 1) * 32;
#pragma unroll
            for (int i = 0; i < 4; i++) {
                const int u = tid + i*256, row = u >> 3, c = u & 7;
                cp16(smBase + off + (uint32_t)(row*144 + c*16),          Ag + (size_t)row*512 + kk + c*4);
                cp16(smBase + off + (uint32_t)(4608*4 + row*144 + c*16), Bg + (size_t)row*512 + kk + c*4);
            }
            CP_COMMIT();
            CP_WAIT1();
        } else {
            CP_WAIT0();
        }
        __syncthreads();

        const uint32_t boff = (uint32_t)(cur * 9216 * 4);
#pragma unroll
        for (int ks = 0; ks < 4; ks++) {
            uint32_t a[2][4], b[8][2];
#pragma unroll
            for (int mt = 0; mt < 2; mt++)
                ldm_x4(a[mt][0], a[mt][1], a[mt][2], a[mt][3],
                       aFB + boff + (uint32_t)(mt*16*36*4 + ks*32));
#pragma unroll
            for (int ntp = 0; ntp < 4; ntp++)
                ldm_x4(b[2*ntp][0], b[2*ntp][1], b[2*ntp+1][0], b[2*ntp+1][1],
                       bFB + boff + (uint32_t)(ntp*16*36*4 + ks*32));
#pragma unroll
            for (int mt = 0; mt < 2; mt++)
#pragma unroll
                for (int nt = 0; nt < 8; nt++)
                    mma_f16(acc[mt][nt], a[mt], b[nt]);
        }
        __syncthreads();
    }

#pragma unroll
    for (int mt = 0; mt < 2; mt++) {
#pragma unroll
        for (int nt = 0; nt < 8; nt++) {
            const int n = bn + wn*64 + nt*8 + 2*t;
            const float bv0 = bias[n], bv1 = bias[n+1];
#pragma unroll
            for (int half = 0; half < 2; half++) {
                const int m = bm + wm*32 + mt*16 + g + half*8;
                const float v0 = acc[mt][nt][half*2+0] + bv0;
                const float v1 = acc[mt][nt][half*2+1] + bv1;
                size_t oi;
                if (which < 3) {
                    const int b_ = m >> 9, s = m & 511, h = n >> 6, d = n & 63;
                    oi = (((size_t)(b_*HH + h))*SS + s)*DD + d;
                } else {
                    oi = (((size_t)(n >> 6))*1024 + m)*DD + (n & 63);
                }
                outp[oi >> 1] = packh2(v0, v1);
            }
        }
    }
}

// ---------------- fused flash kernel: in-place P~, 2-buf V, rolling pos ----
// words: Qs 2304 | Ks 2304 | Ps 4608 | Vs0 2304 | Vs1 2304 | SsF 4352 (P~ alias)
//        | B1 4352 | B2 4352 | m/l/scale 192 | mask 512 = 27584
#define FL_SMEM (27584 * 4)   // 110336 B; x2 = 220672 <= 228KB/SM

__global__ __launch_bounds__(320, 2) void flash_tc(const float* __restrict__ mask,
                                                   float* __restrict__ out)
{
    extern __shared__ uint32_t smw[];
    uint32_t* Qs  = smw;                    // [64 i][36 w]
    uint32_t* Ks  = smw + 2304;             // [64 j][36 w]
    uint32_t* Ps  = smw + 4608;             // [128 p][36 w] rolling band
    uint32_t* Vs0 = smw + 9216;             // [64 j][36 w]
    uint32_t* Vs1 = smw + 11520;            // [64 j][36 w]
    float*    SsF = (float*)(smw + 13824);  // [64][68] CC accum; P~ f16 in-place
    uint32_t* PtU = smw + 13824;            // alias of SsF
    float*    B1  = (float*)(smw + 18176);  // [64][68] sheared CPF
    float*    B2  = (float*)(smw + 22528);  // [64][68] sheared PCF
    float* sm_m     = (float*)(smw + 26880);
    float* sm_l     = sm_m + 64;
    float* sm_scale = sm_m + 128;
    float* sm_mask  = sm_m + 192;           // [512] full mask row

    const int i0 = blockIdx.x * 64;
    const int bh = blockIdx.y;
    const int b_ = bh >> 4, h = bh & 15;
    const int tid = threadIdx.x;
    const int wid = tid >> 5, lane = tid & 31;
    const int g = lane >> 2, t = lane & 3;
    const int wm = wid >> 1, wn = wid & 1;

    const uint32_t* q32 = g_q + ((size_t)bh*SS + i0) * (DD/2);
    const uint32_t* k32 = g_k + (size_t)bh*SS*(DD/2);
    const uint32_t* v32 = g_v + (size_t)bh*SS*(DD/2);
    const uint32_t* p32 = g_pos + (size_t)h * 1024 * (DD/2);

    const uint32_t smQs = smaddr(Qs), smKs = smaddr(Ks), smPs = smaddr(Ps);
    const uint32_t smVs0 = smaddr(Vs0), smVs1 = smaddr(Vs1);

    // prologue: mask + Q + chunk-0 K, full 128-row P band, V0; one group
    for (int u = tid; u < 512; u += 320)
        sm_mask[u] = mask[(size_t)b_*SS + u];
    if (tid < 256) {
#pragma unroll
        for (int i = 0; i < 2; i++) {
            const int u = tid + i*256, row = u >> 3, c = u & 7;
            cp16(smQs + (uint32_t)(row*144 + c*16), q32 + row*32 + c*4);
            cp16(smKs + (uint32_t)(row*144 + c*16), k32 + row*32 + c*4);
            cp16(smVs0 + (uint32_t)(row*144 + c*16), v32 + row*32 + c*4);
        }
        const int base0 = i0 + 449;
#pragma unroll
        for (int i = 0; i < 4; i++) {
            const int u = tid + i*256, pr = u >> 3, c = u & 7;
            int grow = base0 + pr;
            grow = grow < 0 ? 0 : (grow > 1023 ? 1023 : grow);
            cp16(smPs + (uint32_t)(pr*144 + c*16), p32 + grow*32 + c*4);
        }
        CP_COMMIT();
        CP_WAIT0();
    }
    if (tid < 64) { sm_m[tid] = -1e30f; sm_l[tid] = 0.f; }
    __syncthreads();

    float acc_o[4][4];
#pragma unroll
    for (int nt = 0; nt < 4; nt++)
#pragma unroll
        for (int e = 0; e < 4; e++) acc_o[nt][e] = 0.f;

    // score-phase chunk assignment
    int Arow, Brow;
    int kind;
    if (wid < 2)      { Arow = wid*32;          Brow = 0;                 kind = 0; }
    else if (wid < 6) { Arow = ((wid-2)&1)*32;  Brow = ((wid-2)>>1)*64;   kind = 1; }
    else              { Arow = (wid-6)*32;      Brow = 0;                 kind = 2; }

    // fragment bases for both pos-band parities
    uint32_t aFBp[2], bFBp[2];
#pragma unroll
    for (int par = 0; par < 2; par++) {
        const int flip = par ? 64 : 0;
        const int Arow_p = (kind == 2) ? (Arow ^ flip) : Arow;
        const int Brow_p = (kind == 1) ? (Brow ^ flip) : Brow;
        const uint32_t aBase = (kind == 2) ? smPs : smQs;
        const uint32_t bBase = (kind == 1) ? smPs : smKs;
        aFBp[par] = aBase + (uint32_t)(((Arow_p + A_ROW(lane))*36 + A_COL(lane)) * 4);
        bFBp[par] = bBase + (uint32_t)(((Brow_p + B_ROW(lane))*36 + B_COL(lane)) * 4);
    }
    const uint32_t aPV = smaddr(&PtU[(wm*16 + A_ROW(lane))*68 + A_COL(lane)]);
    const uint32_t vOff = (uint32_t)((((lane >> 3) & 1) * 8 + (lane & 7)) * 144
                                     + ((lane >> 4) & 1) * 16 + wn * 64);
    const uint32_t bPVt0 = smVs0 + vOff;
    const uint32_t bPVt1 = smVs1 + vOff;

    const float s1 = 0.14433756729740643f;      // 1/sqrt(48)

    for (int c_ = 0; c_ < 8; c_++) {
        const int j0 = c_ * 64;
        const int par = c_ & 1;
        const uint32_t aFB = aFBp[par];
        const uint32_t bFB = bFBp[par];

        // ---- score MMAs in two nt-halves; shear stores ----
#pragma unroll
        for (int hN = 0; hN < 2; hN++) {
            float acc[2][4][4];
#pragma unroll
            for (int mt = 0; mt < 2; mt++)
#pragma unroll
                for (int nt = 0; nt < 4; nt++)
#pragma unroll
                    for (int e = 0; e < 4; e++) acc[mt][nt][e] = 0.f;

#pragma unroll
            for (int ks = 0; ks < 4; ks++) {
                uint32_t a[2][4], b[4][2];
#pragma unroll
                for (int mt = 0; mt < 2; mt++)
                    ldm_x4(a[mt][0], a[mt][1], a[mt][2], a[mt][3],
                           aFB + (uint32_t)(mt*16*36*4 + ks*32));
#pragma unroll
                for (int ntp = 0; ntp < 2; ntp++)
                    ldm_x4(b[2*ntp][0], b[2*ntp][1], b[2*ntp+1][0], b[2*ntp+1][1],
                           bFB + (uint32_t)((hN*32 + ntp*16)*36*4 + ks*32));
#pragma unroll
                for (int mt = 0; mt < 2; mt++)
#pragma unroll
                    for (int nt = 0; nt < 4; nt++)
                        mma_f16(acc[mt][nt], a[mt], b[nt]);
            }

            if (kind == 0) {
#pragma unroll
                for (int mt = 0; mt < 2; mt++)
#pragma unroll
                    for (int nt = 0; nt < 4; nt++) {
                        const int r0 = Arow + mt*16 + g;
                        const int c0 = (hN*4 + nt)*8 + 2*t;
                        *(float2*)&SsF[r0*68 + c0]     = make_float2(acc[mt][nt][0], acc[mt][nt][1]);
                        *(float2*)&SsF[(r0+8)*68 + c0] = make_float2(acc[mt][nt][2], acc[mt][nt][3]);
                    }
            } else if (kind == 1) {   // CPF[ai][p] -> B1[ai][ai-p+63]
#pragma unroll
                for (int mt = 0; mt < 2; mt++)
#pragma unroll
                    for (int nt = 0; nt < 4; nt++) {
                        const int ai0 = Arow + mt*16 + g;
                        const int p0 = Brow + (hN*4 + nt)*8 + 2*t;
#pragma unroll
                        for (int e = 0; e < 4; e++) {
                            const int ai = ai0 + (e >> 1)*8;
                            const int p  = p0 + (e & 1);
                            const int cj = ai - p + 63;
                            if ((unsigned)cj < 64u)
                                B1[ai*68 + cj] = acc[mt][nt][e];
                        }
                    }
            } else {                  // PCF[r][cj] -> B2[r+cj-63][cj]
#pragma unroll
                for (int mt = 0; mt < 2; mt++)
#pragma unroll
                    for (int nt = 0; nt < 4; nt++) {
                        const int r0 = Arow + mt*16 + g;
                        const int c0 = (hN*4 + nt)*8 + 2*t;
#pragma unroll
                        for (int e = 0; e < 4; e++) {
                            const int r  = r0 + (e >> 1)*8;
                            const int cj = c0 + (e & 1);
                            const int ai = r + cj - 63;
                            if ((unsigned)ai < 64u)
                                B2[ai*68 + cj] = acc[mt][nt][e];
                        }
                    }
            }
        }
        __syncthreads();

        // ---- prefetch next chunk's K, new 64 pos rows, V into other buffer -
        if (c_ < 7 && tid < 256) {
            const uint32_t* kn32 = k32 + (size_t)(j0 + 64) * 32;
            const uint32_t* vn32 = v32 + (size_t)(j0 + 64) * 32;
            const uint32_t smVn = par ? smVs0 : smVs1;   // Vs[par^1]
#pragma unroll
            for (int i = 0; i < 2; i++) {
                const int u = tid + i*256, row = u >> 3, c = u & 7;
                cp16(smKs + (uint32_t)(row*144 + c*16), kn32 + row*32 + c*4);
                cp16(smVn + (uint32_t)(row*144 + c*16), vn32 + row*32 + c*4);
            }
            const int cn = c_ + 1;
            const int basen = i0 - 64*cn + 449;
            const int poff = (cn & 1) ? 64 : 0;   // phys slot of new logical [0,64)
#pragma unroll
            for (int i = 0; i < 2; i++) {
                const int u = tid + i*256, pr = u >> 3, c = u & 7;   // pr 0..63
                int grow = basen + pr;
                grow = grow < 0 ? 0 : (grow > 1023 ? 1023 : grow);
                cp16(smPs + (uint32_t)((pr + poff)*144 + c*16), p32 + grow*32 + c*4);
            }
            CP_COMMIT();
        }

        // ---- online softmax (threads 0..255); P~ f16 written IN PLACE ----
        if (tid < 256) {
            const int row = tid >> 2, q4 = tid & 3;
            const int c0 = q4*16;
            float v[16];
            float mloc = -1e30f;
#pragma unroll
            for (int i4 = 0; i4 < 4; i4++) {
                const float4 sc = *(const float4*)&SsF[row*68 + c0 + 4*i4];
                const float4 y2 = *(const float4*)&B2[row*68 + c0 + 4*i4];
                const float4 y1 = *(const float4*)&B1[row*68 + c0 + 4*i4];
                const float4 mk = *(const float4*)&sm_mask[j0 + c0 + 4*i4];
                v[4*i4+0] = (sc.x + y2.x + 0.125f*y1.x) * s1 + mk.x;
                v[4*i4+1] = (sc.y + y2.y + 0.125f*y1.y) * s1 + mk.y;
                v[4*i4+2] = (sc.z + y2.z + 0.125f*y1.z) * s1 + mk.z;
                v[4*i4+3] = (sc.w + y2.w + 0.125f*y1.w) * s1 + mk.w;
                mloc = fmaxf(mloc, fmaxf(fmaxf(v[4*i4], v[4*i4+1]), fmaxf(v[4*i4+2], v[4*i4+3])));
            }
            mloc = fmaxf(mloc, __shfl_xor_sync(0xffffffffu, mloc, 1));
            mloc = fmaxf(mloc, __shfl_xor_sync(0xffffffffu, mloc, 2));
            const float mold = sm_m[row];
            const float mnew = fmaxf(mold, mloc);
            float lsum = 0.f;
#pragma unroll
            for (int i = 0; i < 8; i++) {
                const float e0 = __expf(v[2*i]   - mnew);
                const float e1 = __expf(v[2*i+1] - mnew);
                PtU[row*68 + q4*8 + i] = packh2(e0, e1);
                lsum += e0 + e1;
            }
            lsum += __shfl_xor_sync(0xffffffffu, lsum, 1);
            lsum += __shfl_xor_sync(0xffffffffu, lsum, 2);
            if (q4 == 0) {
                const float sc = __expf(mold - mnew);
                sm_m[row] = mnew;
                sm_scale[row] = sc;
                sm_l[row] = sm_l[row] * sc + lsum;
            }
        }
        __syncthreads();

        // ---- PV: warps 0..7, reads in-place P~ (stride 68) + Vs[par] ------
        if (wid < 8) {
            const float sc0 = sm_scale[wm*16 + g];
            const float sc1 = sm_scale[wm*16 + g + 8];
            const uint32_t bPVt = par ? bPVt1 : bPVt0;
#pragma unroll
            for (int nt = 0; nt < 4; nt++) {
                acc_o[nt][0] *= sc0; acc_o[nt][1] *= sc0;
                acc_o[nt][2] *= sc1; acc_o[nt][3] *= sc1;
            }
#pragma unroll
            for (int ks = 0; ks < 4; ks++) {
                uint32_t a[4], b[4][2];
                ldm_x4(a[0], a[1], a[2], a[3], aPV + (uint32_t)(ks*32));
#pragma unroll
                for (int ntp = 0; ntp < 2; ntp++)
                    ldm_x4_t(b[2*ntp][0], b[2*ntp][1], b[2*ntp+1][0], b[2*ntp+1][1],
                             bPVt + (uint32_t)(ks*16*144 + ntp*32));
#pragma unroll
                for (int nt = 0; nt < 4; nt++)
                    mma_f16(acc_o[nt], a, b[nt]);
            }
        }
        if (c_ < 7 && tid < 256) CP_WAIT0();   // drain next chunk's K/P/V
        __syncthreads();                        // entry barrier for next chunk
    }

    // ---- finalize: out[i][d] = acc_o / l ----
    if (wid < 8) {
        const int r0 = wm*16 + g;
        const float inv0 = 1.f / sm_l[r0];
        const float inv1 = 1.f / sm_l[r0 + 8];
#pragma unroll
        for (int nt = 0; nt < 4; nt++) {
            const int col = wn*32 + nt*8 + 2*t;
            const size_t o0 = ((size_t)b_*SS + i0 + r0)*HIDN + h*DD + col;
            const size_t o1 = ((size_t)b_*SS + i0 + r0 + 8)*HIDN + h*DD + col;
            *(float2*)(out + o0) = make_float2(acc_o[nt][0]*inv0, acc_o[nt][1]*inv0);
            *(float2*)(out + o1) = make_float2(acc_o[nt][2]*inv1, acc_o[nt][3]*inv1);
        }
    }
}

// ---------------- launch ---------------------------------------------------
extern "C" void kernel_launch(void* const* d_in, const int* in_sizes, int n_in,
                              void* d_out, int out_size)
{
    const float* hs  = (const float*)d_in[0];
    const float* msk = (const float*)d_in[1];
    const float* Wq  = (const float*)d_in[3];
    const float* bq  = (const float*)d_in[4];
    const float* Wk  = (const float*)d_in[5];
    const float* bk  = (const float*)d_in[6];
    const float* Wv  = (const float*)d_in[7];
    const float* bv  = (const float*)d_in[8];
    const float* Wpk = (const float*)d_in[9];
    const float* bpk = (const float*)d_in[10];
    const float* rel = (const float*)d_in[11];
    float* out = (float*)d_out;

    cudaFuncSetAttribute(flash_tc, cudaFuncAttributeMaxDynamicSharedMemorySize, FL_SMEM);

    dim3 gc(1024, 6);                     // fp32 -> fp16 one-time convert (64B/thr)
    precvt<<<gc, 256>>>(hs, rel, Wq, Wk, Wv, Wpk);

    dim3 gg(8, 32, 4);                    // z: Wq, Wk, Wv, Wpk (y>=8 idles for z=3)
    gemm_tc<<<gg, 256>>>(bq, bk, bv, bpk);

    dim3 gf(SS/64, BH);                   // (8, 128)
    flash_tc<<<gf, 320, FL_SMEM>>>(msk, out);
}